// round 3
// baseline (speedup 1.0000x reference)
#include <cuda_runtime.h>
#include <math.h>
#include <stdint.h>

#define NAT   50000
#define NP    1000000
#define MSGS  104          // msg row stride (97 used)
#define NSM   152          // GB300 SM count

// ---------------- device scratch (static, allocation-free) ----------------
__device__ float4 g_Msum[NAT * 34];            // 136 packed upper-tri floats / atom
__device__ float  g_S[NAT];
__device__ float  g_msg[(size_t)NAT * MSGS];   // [0:64)=emb*S, [64:96)=Q, [96]=q*S

// ---------------- helpers ----------------
__device__ __forceinline__ void red4(float4* addr, float a, float b, float c, float d) {
    asm volatile("red.global.add.v4.f32 [%0], {%1, %2, %3, %4};"
                 :: "l"(addr), "f"(a), "f"(b), "f"(c), "f"(d) : "memory");
}

__device__ __forceinline__ float gelu_exact(float x) {
    return 0.5f * x * (1.0f + erff(x * 0.70710678118654752440f));
}
__device__ __forceinline__ float4 gelu4(float4 v) {
    return make_float4(gelu_exact(v.x), gelu_exact(v.y), gelu_exact(v.z), gelu_exact(v.w));
}

// ---------------- kernel 0: zero accumulators ----------------
__global__ void k_zero() {
    int i = blockIdx.x * blockDim.x + threadIdx.x;
    if (i < NAT * 34) g_Msum[i] = make_float4(0.f, 0.f, 0.f, 0.f);
    if (i < NAT)      g_S[i] = 0.f;
}

// ---------------- kernel 1: per-pair Gram scatter ----------------
// thread-per-pair. M_p = sum_d gv_d gv_d^T (136 upper-tri entries), s = sum(gs),
// scattered into per-atom accumulators with vector REDs. idx is INT32.
__global__ void __launch_bounds__(256) k_pairs(const float* __restrict__ gs,
                                               const float* __restrict__ gv,
                                               const int* __restrict__ idxj) {
    int p = blockIdx.x * 256 + threadIdx.x;
    if (p >= NP) return;

    float v[48];
    const float4* gv4 = reinterpret_cast<const float4*>(gv) + (size_t)p * 12;
#pragma unroll
    for (int k = 0; k < 12; k++) {
        float4 t = __ldg(gv4 + k);
        v[4*k] = t.x; v[4*k+1] = t.y; v[4*k+2] = t.z; v[4*k+3] = t.w;
    }
    const float4* gs4 = reinterpret_cast<const float4*>(gs) + (size_t)p * 4;
    float s = 0.f;
#pragma unroll
    for (int k = 0; k < 4; k++) {
        float4 t = __ldg(gs4 + k);
        s += (t.x + t.y) + (t.z + t.w);
    }
    int a = __ldg(idxj + p);
    if (a < 0 || a >= NAT) return;   // defensive

    float4* mrow = g_Msum + (size_t)a * 34;
    float buf[4];
    int e = 0;
#pragma unroll
    for (int g = 0; g < 16; ++g) {
#pragma unroll
        for (int gp = g; gp < 16; ++gp) {
            buf[e & 3] = v[g] * v[gp] + v[16+g] * v[16+gp] + v[32+g] * v[32+gp];
            if ((e & 3) == 3)
                red4(mrow + (e >> 2), buf[0], buf[1], buf[2], buf[3]);
            ++e;
        }
    }
    atomicAdd(g_S + a, s);
}

// ---------------- kernel 2: per-atom T + quadratic form -> msg ----------------
__global__ void __launch_bounds__(256) k_atom(const float* __restrict__ emb,
                                              const float* __restrict__ pc,
                                              const float* __restrict__ agh) {
    extern __shared__ float aghs[];
    int tid = threadIdx.x;
    {
        const float4* a4 = reinterpret_cast<const float4*>(agh);
        float4* s4 = reinterpret_cast<float4*>(aghs);
        for (int i = tid; i < 8192; i += 256) s4[i] = __ldg(a4 + i);
    }
    __syncthreads();

    int lane = tid & 31, wid = tid >> 5;
    int gw = blockIdx.x * 8 + wid;
    int GW = gridDim.x * 8;

    for (int base = gw * 4; base < NAT; base += GW * 4) {
        float e0[4], e1[4];
#pragma unroll
        for (int i = 0; i < 4; i++) {
            int ai = (base + i < NAT) ? base + i : NAT - 1;
            e0[i] = __ldg(emb + (size_t)ai * 64 + lane);
            e1[i] = __ldg(emb + (size_t)ai * 64 + 32 + lane);
        }

        float T[4][16];
#pragma unroll
        for (int i = 0; i < 4; i++)
#pragma unroll
            for (int g = 0; g < 16; g++) T[i][g] = 0.f;

#pragma unroll 4
        for (int f = 0; f < 64; f++) {
            float ef0 = __shfl_sync(0xffffffffu, (f < 32) ? e0[0] : e1[0], f & 31);
            float ef1 = __shfl_sync(0xffffffffu, (f < 32) ? e0[1] : e1[1], f & 31);
            float ef2 = __shfl_sync(0xffffffffu, (f < 32) ? e0[2] : e1[2], f & 31);
            float ef3 = __shfl_sync(0xffffffffu, (f < 32) ? e0[3] : e1[3], f & 31);
            const float* ap = aghs + f * 512 + lane;
#pragma unroll
            for (int g = 0; g < 16; g++) {
                float av = ap[g * 32];
                T[0][g] = fmaf(ef0, av, T[0][g]);
                T[1][g] = fmaf(ef1, av, T[1][g]);
                T[2][g] = fmaf(ef2, av, T[2][g]);
                T[3][g] = fmaf(ef3, av, T[3][g]);
            }
        }

#pragma unroll
        for (int i = 0; i < 4; i++) {
            int a = base + i;
            if (a < NAT) {
                const float* mr = reinterpret_cast<const float*>(g_Msum) + (size_t)a * 136;
                float mv0 = mr[lane], mv1 = mr[32 + lane], mv2 = mr[64 + lane], mv3 = mr[96 + lane];
                float mv4 = (lane < 8) ? mr[128 + lane] : 0.f;
                float Sv = g_S[a];
                float qv = __ldg(pc + a);

                float qd = 0.f, qo = 0.f;
                int e = 0;
#pragma unroll
                for (int g = 0; g < 16; g++) {
#pragma unroll
                    for (int gp = g; gp < 16; gp++) {
                        float msrc = (e < 32) ? mv0 : (e < 64) ? mv1 : (e < 96) ? mv2
                                    : (e < 128) ? mv3 : mv4;      // e is compile-time
                        float m = __shfl_sync(0xffffffffu, msrc, e & 31);
                        float t = T[i][g] * T[i][gp];
                        if (g == gp) qd = fmaf(m, t, qd);
                        else         qo = fmaf(m, t, qo);
                        ++e;
                    }
                }
                float Q = fmaf(2.f, qo, qd);

                float* mg = g_msg + (size_t)a * MSGS;
                mg[lane]      = e0[i] * Sv;
                mg[32 + lane] = e1[i] * Sv;
                mg[64 + lane] = Q;
                if (lane == 0) mg[96] = qv * Sv;
            }
        }
    }
}

// ---------------- kernel 3: MLP (97->128->128->66) + output scatter ----------------
#define oW1 0
#define oW2 12416
#define oW3 28800          /* 8448 used + 64 zero pad */
#define oB1 37312
#define oB2 37440
#define oB3 37568          /* 68 (66 + pad) */
#define oHS 37636          /* 8 warps * 4 atoms * 128 */
#define oMS 41732          /* 8 warps * 4 atoms * 97  */
#define SMEM_MLP ((44836) * 4)

__global__ void __launch_bounds__(256) k_mlp(const float* __restrict__ W1,
                                             const float* __restrict__ b1,
                                             const float* __restrict__ W2,
                                             const float* __restrict__ b2,
                                             const float* __restrict__ W3,
                                             const float* __restrict__ b3,
                                             float* __restrict__ out) {
    extern __shared__ float sm[];
    int tid = threadIdx.x;
    for (int i = tid; i < 97 * 128; i += 256) sm[oW1 + i] = W1[i];
    for (int i = tid; i < 128 * 128; i += 256) sm[oW2 + i] = W2[i];
    for (int i = tid; i < 8512; i += 256) sm[oW3 + i] = (i < 8448) ? W3[i] : 0.f;
    if (tid < 128) { sm[oB1 + tid] = b1[tid]; sm[oB2 + tid] = b2[tid]; }
    if (tid < 68)  sm[oB3 + tid] = (tid < 66) ? b3[tid] : 0.f;
    __syncthreads();

    int lane = tid & 31, w = tid >> 5;
    float* ms = sm + oMS + w * 4 * 97;
    float* hs = sm + oHS + w * 4 * 128;
    const float4* W1v = reinterpret_cast<const float4*>(sm + oW1);
    const float4* W2v = reinterpret_cast<const float4*>(sm + oW2);
    float4 bv1 = reinterpret_cast<const float4*>(sm + oB1)[lane];
    float4 bv2 = reinterpret_cast<const float4*>(sm + oB2)[lane];
    float bc0 = sm[oB3 + lane];
    float bc1 = sm[oB3 + 32 + lane];
    float bc2 = (lane < 2) ? sm[oB3 + 64 + lane] : 0.f;

    float* da = out;
    float* dq = out + (size_t)NAT * 64;
    float* fo = out + (size_t)NAT * 65;

    int gw = blockIdx.x * 8 + w, GW = gridDim.x * 8;
    for (int base = gw * 4; base < NAT; base += GW * 4) {
#pragma unroll
        for (int i = 0; i < 4; i++) {
            int ai = (base + i < NAT) ? base + i : NAT - 1;
            const float* mrow = g_msg + (size_t)ai * MSGS;
            for (int j = lane; j < 97; j += 32) ms[i * 97 + j] = mrow[j];
        }
        __syncwarp();

        // ---- layer 1 ----
        float4 acc[4];
#pragma unroll
        for (int i = 0; i < 4; i++) acc[i] = bv1;
#pragma unroll 2
        for (int k = 0; k < 97; k++) {
            float4 wv = W1v[k * 32 + lane];
#pragma unroll
            for (int i = 0; i < 4; i++) {
                float x = ms[i * 97 + k];
                acc[i].x = fmaf(wv.x, x, acc[i].x);
                acc[i].y = fmaf(wv.y, x, acc[i].y);
                acc[i].z = fmaf(wv.z, x, acc[i].z);
                acc[i].w = fmaf(wv.w, x, acc[i].w);
            }
        }
        __syncwarp();
#pragma unroll
        for (int i = 0; i < 4; i++)
            reinterpret_cast<float4*>(hs + i * 128)[lane] = gelu4(acc[i]);
        __syncwarp();

        // ---- layer 2 ----
        float4 a2[4];
#pragma unroll
        for (int i = 0; i < 4; i++) a2[i] = bv2;
#pragma unroll 2
        for (int k = 0; k < 128; k++) {
            float4 wv = W2v[k * 32 + lane];
#pragma unroll
            for (int i = 0; i < 4; i++) {
                float x = hs[i * 128 + k];
                a2[i].x = fmaf(wv.x, x, a2[i].x);
                a2[i].y = fmaf(wv.y, x, a2[i].y);
                a2[i].z = fmaf(wv.z, x, a2[i].z);
                a2[i].w = fmaf(wv.w, x, a2[i].w);
            }
        }
        __syncwarp();
#pragma unroll
        for (int i = 0; i < 4; i++)
            reinterpret_cast<float4*>(hs + i * 128)[lane] = gelu4(a2[i]);
        __syncwarp();

        // ---- layer 3 (66 cols) ----
        float c0[4], c1[4], c2[4];
#pragma unroll
        for (int i = 0; i < 4; i++) { c0[i] = bc0; c1[i] = bc1; c2[i] = bc2; }
#pragma unroll 2
        for (int k = 0; k < 128; k++) {
            const float* wr = sm + oW3 + k * 66;
            float w0 = wr[lane], w1 = wr[32 + lane], w2 = wr[64 + lane]; // pad-safe
#pragma unroll
            for (int i = 0; i < 4; i++) {
                float x = hs[i * 128 + k];
                c0[i] = fmaf(w0, x, c0[i]);
                c1[i] = fmaf(w1, x, c1[i]);
                c2[i] = fmaf(w2, x, c2[i]);
            }
        }

        // ---- scatter: col0=delta_q, col1=f, cols 2..65 = delta_a ----
#pragma unroll
        for (int i = 0; i < 4; i++) {
            int a = base + i;
            if (a >= NAT) break;
            if (lane == 0)      dq[a] = c0[i];
            else if (lane == 1) fo[a] = c0[i];
            else                da[(size_t)a * 64 + (lane - 2)] = c0[i];
            da[(size_t)a * 64 + (30 + lane)] = c1[i];
            if (lane < 2) da[(size_t)a * 64 + (62 + lane)] = c2[i];
        }
    }
}

// ---------------- host launcher ----------------
// Inputs resolved by ELEMENT COUNT (order-agnostic). pair_indices is INT32 on
// device (JAX x64 disabled downgrades jnp.int64 -> int32).
extern "C" void kernel_launch(void* const* d_in, const int* in_sizes, int n_in,
                              void* d_out, int out_size) {
    const float *emb = 0, *pc = 0, *gs = 0, *gv = 0, *agh = 0;
    const float *W1 = 0, *b1 = 0, *W2 = 0, *b2 = 0, *W3 = 0, *b3 = 0;
    const int* pidx = 0;

    for (int i = 0; i < n_in; i++) {
        switch (in_sizes[i]) {
            case 3200000:  emb = (const float*)d_in[i]; break;     // 50000 x 64
            case 50000:    pc  = (const float*)d_in[i]; break;     // 50000 x 1
            case 16000000: gs  = (const float*)d_in[i]; break;     // 1e6 x 16
            case 48000000: gv  = (const float*)d_in[i]; break;     // 1e6 x 3 x 16
            case 32768:    agh = (const float*)d_in[i]; break;     // 64 x 16 x 32
            case 16512:    W1  = (const float*)d_in[i]; break;     // 129 x 128
            case 16384:    W2  = (const float*)d_in[i]; break;     // 128 x 128
            case 8448:     W3  = (const float*)d_in[i]; break;     // 128 x 66
            case 128:      if (!b1) b1 = (const float*)d_in[i];
                           else     b2 = (const float*)d_in[i]; break;
            case 66:       b3  = (const float*)d_in[i]; break;
            case 2000000:  pidx = (const int*)d_in[i]; break;      // 2 x 1e6 int32
            default: break;
        }
    }
    float* out = (float*)d_out;
    (void)out_size;

    cudaFuncSetAttribute(k_atom, cudaFuncAttributeMaxDynamicSharedMemorySize, 131072);
    cudaFuncSetAttribute(k_mlp,  cudaFuncAttributeMaxDynamicSharedMemorySize, SMEM_MLP);

    k_zero<<<(NAT * 34 + 255) / 256, 256>>>();
    k_pairs<<<(NP + 255) / 256, 256>>>(gs, gv, pidx + NP);   // idx_j = pair_indices[1]
    k_atom<<<NSM, 256, 131072>>>(emb, pc, agh);
    k_mlp<<<NSM, 256, SMEM_MLP>>>(W1, b1, W2, b2, W3, b3, out);
}

// round 4
// speedup vs baseline: 1.0678x; 1.0678x over previous
#include <cuda_runtime.h>
#include <math.h>
#include <stdint.h>

#define NAT   50000
#define NP    1000000
#define MSGS  104
#define NSM   152

// ---------------- device scratch ----------------
__device__ float g_Msum[(size_t)NAT * 136];
__device__ float g_S[NAT];
__device__ float g_msg[(size_t)NAT * MSGS];
__device__ int   g_cnt[NAT];
__device__ int   g_off[NAT + 1];
__device__ int   g_cur[NAT];
__device__ int   g_plist[NP];

// ---------------- f32x2 helpers ----------------
__device__ __forceinline__ unsigned long long pack2(float x, float y) {
    unsigned long long r; asm("mov.b64 %0, {%1, %2};" : "=l"(r) : "f"(x), "f"(y)); return r;
}
__device__ __forceinline__ unsigned long long dup2(float x) {
    unsigned long long r; asm("mov.b64 %0, {%1, %1};" : "=l"(r) : "f"(x)); return r;
}
__device__ __forceinline__ void unpack2(unsigned long long v, float& x, float& y) {
    asm("mov.b64 {%0, %1}, %2;" : "=f"(x), "=f"(y) : "l"(v));
}
__device__ __forceinline__ unsigned long long fma2(unsigned long long a, unsigned long long b,
                                                   unsigned long long c) {
    unsigned long long d;
    asm("fma.rn.f32x2 %0, %1, %2, %3;" : "=l"(d) : "l"(a), "l"(b), "l"(c));
    return d;
}

__device__ __forceinline__ float gelu_exact(float x) {
    return 0.5f * x * (1.0f + erff(x * 0.70710678118654752440f));
}

// upper-tri index (compile-time under full unroll)
#define EIDX(g, gp) ((g) * 16 - ((g) * ((g) - 1)) / 2 + ((gp) - (g)))

// ---------------- k_zero ----------------
__global__ void k_zero() {
    int i = blockIdx.x * blockDim.x + threadIdx.x;
    if (i < NAT) { g_cnt[i] = 0; g_S[i] = 0.f; }
}

// ---------------- k_hist: count pairs per atom + S accumulation ----------------
__global__ void __launch_bounds__(256) k_hist(const float* __restrict__ gs,
                                              const int* __restrict__ idxj) {
    int p = blockIdx.x * 256 + threadIdx.x;
    if (p >= NP) return;
    const float4* gs4 = reinterpret_cast<const float4*>(gs) + (size_t)p * 4;
    float s = 0.f;
#pragma unroll
    for (int k = 0; k < 4; k++) {
        float4 t = __ldg(gs4 + k);
        s += (t.x + t.y) + (t.z + t.w);
    }
    int a = __ldg(idxj + p);
    if (a < 0 || a >= NAT) return;
    atomicAdd(&g_cnt[a], 1);
    atomicAdd(&g_S[a], s);
}

// ---------------- k_scan: exclusive prefix (1 block, 1024 threads) ----------------
__global__ void __launch_bounds__(1024) k_scan() {
    __shared__ int ts[1024];
    int t = threadIdx.x;
    const int CH = (NAT + 1023) / 1024;   // 49
    int base = t * CH;
    int s0 = 0, s1 = 0, s2 = 0, s3 = 0;
    for (int j = 0; j + 3 < CH; j += 4) {
        int a = base + j;
        s0 += (a + 0 < NAT) ? g_cnt[a + 0] : 0;
        s1 += (a + 1 < NAT) ? g_cnt[a + 1] : 0;
        s2 += (a + 2 < NAT) ? g_cnt[a + 2] : 0;
        s3 += (a + 3 < NAT) ? g_cnt[a + 3] : 0;
    }
    for (int j = CH & ~3; j < CH; j++) {
        int a = base + j;
        s0 += (a < NAT) ? g_cnt[a] : 0;
    }
    ts[t] = s0 + s1 + s2 + s3;
    __syncthreads();
    for (int off = 1; off < 1024; off <<= 1) {
        int v = (t >= off) ? ts[t - off] : 0;
        __syncthreads();
        ts[t] += v;
        __syncthreads();
    }
    int run = (t == 0) ? 0 : ts[t - 1];
    for (int j = 0; j < CH; j++) {
        int a = base + j;
        if (a < NAT) {
            g_off[a] = run;
            g_cur[a] = run;
            run += g_cnt[a];
        } else if (a == NAT) {
            g_off[NAT] = run;
        }
    }
}

// ---------------- k_place: bucket pair ids ----------------
__global__ void __launch_bounds__(256) k_place(const int* __restrict__ idxj) {
    int p = blockIdx.x * 256 + threadIdx.x;
    if (p >= NP) return;
    int a = __ldg(idxj + p);
    if (a < 0 || a >= NAT) return;
    int pos = atomicAdd(&g_cur[a], 1);
    g_plist[pos] = p;
}

// ---------------- k_gather: per-atom Gram accumulation (no atomics) ----------------
// t < NAT: half 0 (entries 0..67); t >= NAT: half 1 (entries 68..135).
__global__ void __launch_bounds__(256) k_gather(const float* __restrict__ gv) {
    int t = blockIdx.x * 256 + threadIdx.x;
    if (t >= 2 * NAT) return;
    int half = (t >= NAT) ? 1 : 0;
    int a = half ? (t - NAT) : t;

    float acc[68];
#pragma unroll
    for (int i = 0; i < 68; i++) acc[i] = 0.f;

    int beg = g_off[a], end = g_off[a + 1];

    if (!half) {
        for (int j = beg; j < end; j++) {
            int p = g_plist[j];
            float v[48];
            const float4* gv4 = reinterpret_cast<const float4*>(gv) + (size_t)p * 12;
#pragma unroll
            for (int k = 0; k < 12; k++) {
                float4 q = __ldg(gv4 + k);
                v[4 * k] = q.x; v[4 * k + 1] = q.y; v[4 * k + 2] = q.z; v[4 * k + 3] = q.w;
            }
#pragma unroll
            for (int g = 0; g < 16; g++)
#pragma unroll
                for (int gp = g; gp < 16; gp++) {
                    const int e = EIDX(g, gp);
                    if (e < 68) {
                        float m = v[g] * v[gp] + v[16 + g] * v[16 + gp] + v[32 + g] * v[32 + gp];
                        acc[e] += m;
                    }
                }
        }
    } else {
        for (int j = beg; j < end; j++) {
            int p = g_plist[j];
            float v[48];
            const float4* gv4 = reinterpret_cast<const float4*>(gv) + (size_t)p * 12;
#pragma unroll
            for (int k = 0; k < 12; k++) {
                float4 q = __ldg(gv4 + k);
                v[4 * k] = q.x; v[4 * k + 1] = q.y; v[4 * k + 2] = q.z; v[4 * k + 3] = q.w;
            }
#pragma unroll
            for (int g = 0; g < 16; g++)
#pragma unroll
                for (int gp = g; gp < 16; gp++) {
                    const int e = EIDX(g, gp);
                    if (e >= 68) {
                        float m = v[g] * v[gp] + v[16 + g] * v[16 + gp] + v[32 + g] * v[32 + gp];
                        acc[e - 68] += m;
                    }
                }
        }
    }

    float4* mr4 = reinterpret_cast<float4*>(g_Msum + (size_t)a * 136 + half * 68);
#pragma unroll
    for (int i = 0; i < 17; i++)
        mr4[i] = make_float4(acc[4 * i], acc[4 * i + 1], acc[4 * i + 2], acc[4 * i + 3]);
}

// ---------------- k_atom: T = emb @ agh (f32x2), quad form -> msg ----------------
// agh in smem, relaid as [f][g2][h][2] so (g,g+1) pairs are contiguous b64.
__global__ void __launch_bounds__(512) k_atom(const float* __restrict__ emb,
                                              const float* __restrict__ pc,
                                              const float* __restrict__ agh) {
    extern __shared__ float aghs[];
    int tid = threadIdx.x;
    for (int i = tid; i < 32768; i += 512) {
        int f = i >> 9, rem = i & 511, g = rem >> 5, h = rem & 31;
        aghs[f * 512 + (g >> 1) * 64 + h * 2 + (g & 1)] = __ldg(agh + i);
    }
    __syncthreads();

    int lane = tid & 31, wid = tid >> 5;
    int gw = blockIdx.x * 16 + wid;
    int GW = gridDim.x * 16;

    for (int base = gw * 4; base < NAT; base += GW * 4) {
        float e0[4], e1[4];
#pragma unroll
        for (int i = 0; i < 4; i++) {
            int ai = (base + i < NAT) ? base + i : NAT - 1;
            e0[i] = __ldg(emb + (size_t)ai * 64 + lane);
            e1[i] = __ldg(emb + (size_t)ai * 64 + 32 + lane);
        }

        unsigned long long T2[4][8];
#pragma unroll
        for (int i = 0; i < 4; i++)
#pragma unroll
            for (int g2 = 0; g2 < 8; g2++) T2[i][g2] = 0ull;

        // f = 0..31 from e0, f = 32..63 from e1
#pragma unroll 4
        for (int fl = 0; fl < 32; fl++) {
            unsigned long long x0 = dup2(__shfl_sync(0xffffffffu, e0[0], fl));
            unsigned long long x1 = dup2(__shfl_sync(0xffffffffu, e0[1], fl));
            unsigned long long x2 = dup2(__shfl_sync(0xffffffffu, e0[2], fl));
            unsigned long long x3 = dup2(__shfl_sync(0xffffffffu, e0[3], fl));
            const unsigned long long* ap =
                reinterpret_cast<const unsigned long long*>(aghs + fl * 512) + lane;
#pragma unroll
            for (int g2 = 0; g2 < 8; g2++) {
                unsigned long long av = ap[g2 * 32];
                T2[0][g2] = fma2(x0, av, T2[0][g2]);
                T2[1][g2] = fma2(x1, av, T2[1][g2]);
                T2[2][g2] = fma2(x2, av, T2[2][g2]);
                T2[3][g2] = fma2(x3, av, T2[3][g2]);
            }
        }
#pragma unroll 4
        for (int fl = 0; fl < 32; fl++) {
            unsigned long long x0 = dup2(__shfl_sync(0xffffffffu, e1[0], fl));
            unsigned long long x1 = dup2(__shfl_sync(0xffffffffu, e1[1], fl));
            unsigned long long x2 = dup2(__shfl_sync(0xffffffffu, e1[2], fl));
            unsigned long long x3 = dup2(__shfl_sync(0xffffffffu, e1[3], fl));
            const unsigned long long* ap =
                reinterpret_cast<const unsigned long long*>(aghs + (32 + fl) * 512) + lane;
#pragma unroll
            for (int g2 = 0; g2 < 8; g2++) {
                unsigned long long av = ap[g2 * 32];
                T2[0][g2] = fma2(x0, av, T2[0][g2]);
                T2[1][g2] = fma2(x1, av, T2[1][g2]);
                T2[2][g2] = fma2(x2, av, T2[2][g2]);
                T2[3][g2] = fma2(x3, av, T2[3][g2]);
            }
        }

#pragma unroll
        for (int i = 0; i < 4; i++) {
            int a = base + i;
            if (a >= NAT) break;
            float T[16];
#pragma unroll
            for (int g2 = 0; g2 < 8; g2++) unpack2(T2[i][g2], T[2 * g2], T[2 * g2 + 1]);

            const float* mr = g_Msum + (size_t)a * 136;
            float mv0 = mr[lane], mv1 = mr[32 + lane], mv2 = mr[64 + lane], mv3 = mr[96 + lane];
            float mv4 = (lane < 8) ? mr[128 + lane] : 0.f;
            float Sv = g_S[a];
            float qv = __ldg(pc + a);

            float qd = 0.f, qo = 0.f;
#pragma unroll
            for (int g = 0; g < 16; g++)
#pragma unroll
                for (int gp = g; gp < 16; gp++) {
                    const int e = EIDX(g, gp);
                    float msrc = (e < 32) ? mv0 : (e < 64) ? mv1 : (e < 96) ? mv2
                               : (e < 128) ? mv3 : mv4;
                    float m = __shfl_sync(0xffffffffu, msrc, e & 31);
                    float t = T[g] * T[gp];
                    if (g == gp) qd = fmaf(m, t, qd);
                    else         qo = fmaf(m, t, qo);
                }
            float Q = fmaf(2.f, qo, qd);

            float* mg = g_msg + (size_t)a * MSGS;
            mg[lane]      = e0[i] * Sv;
            mg[32 + lane] = e1[i] * Sv;
            mg[64 + lane] = Q;
            if (lane < 8) mg[96 + lane] = (lane == 0) ? qv * Sv : 0.f;
        }
    }
}

// ---------------- k_mlp: 97->128->128->66 with f32x2, 512 threads ----------------
#define oW1 0              /* 100 x 128 (rows 97..99 zero)      */
#define oW2 12800          /* 128 x 128                          */
#define oW3 29184          /* 128 x 66 + 64 pad                  */
#define oB1 37696
#define oB2 37824
#define oB3 37952          /* 72 (66 + pad)                      */
#define oHS 38024          /* 16 warps * 4 atoms * 128           */
#define oMS 46216          /* 16 warps * 4 atoms * 104           */
#define SMEM_MLP (52872 * 4)

__global__ void __launch_bounds__(512) k_mlp(const float* __restrict__ W1,
                                             const float* __restrict__ b1,
                                             const float* __restrict__ W2,
                                             const float* __restrict__ b2,
                                             const float* __restrict__ W3,
                                             const float* __restrict__ b3,
                                             float* __restrict__ out) {
    extern __shared__ float sm[];
    int tid = threadIdx.x;
    for (int i = tid; i < 12800; i += 512) sm[oW1 + i] = (i < 12416) ? W1[i] : 0.f;
    for (int i = tid; i < 16384; i += 512) sm[oW2 + i] = W2[i];
    for (int i = tid; i < 8512; i += 512) sm[oW3 + i] = (i < 8448) ? W3[i] : 0.f;
    if (tid < 128) { sm[oB1 + tid] = b1[tid]; sm[oB2 + tid] = b2[tid]; }
    if (tid < 72)  sm[oB3 + tid] = (tid < 66) ? b3[tid] : 0.f;
    __syncthreads();

    int lane = tid & 31, w = tid >> 5;
    float* ms = sm + oMS + w * 416;
    float* hs = sm + oHS + w * 512;
    float4 bv1 = reinterpret_cast<const float4*>(sm + oB1)[lane];
    float4 bv2 = reinterpret_cast<const float4*>(sm + oB2)[lane];
    float bc0 = sm[oB3 + lane];
    float bc1 = sm[oB3 + 32 + lane];
    float bc2 = (lane < 2) ? sm[oB3 + 64 + lane] : 0.f;

    float* da = out;
    float* dq = out + (size_t)NAT * 64;
    float* fo = out + (size_t)NAT * 65;

    int gw = blockIdx.x * 16 + w, GW = gridDim.x * 16;
    for (int base = gw * 4; base < NAT; base += GW * 4) {
#pragma unroll
        for (int i = 0; i < 4; i++) {
            int ai = (base + i < NAT) ? base + i : NAT - 1;
            const float4* mrow = reinterpret_cast<const float4*>(g_msg + (size_t)ai * MSGS);
            if (lane < 26) reinterpret_cast<float4*>(ms + i * 104)[lane] = __ldg(mrow + lane);
        }
        __syncwarp();

        // ---- layer 1 (100 rows incl. zero pad) ----
        unsigned long long acc[4][2];
#pragma unroll
        for (int i = 0; i < 4; i++) {
            acc[i][0] = pack2(bv1.x, bv1.y);
            acc[i][1] = pack2(bv1.z, bv1.w);
        }
        for (int k = 0; k < 100; k += 4) {
            float x4[4][4];
#pragma unroll
            for (int i = 0; i < 4; i++) {
                float4 q = *reinterpret_cast<const float4*>(ms + i * 104 + k);
                x4[i][0] = q.x; x4[i][1] = q.y; x4[i][2] = q.z; x4[i][3] = q.w;
            }
#pragma unroll
            for (int j = 0; j < 4; j++) {
                ulonglong2 wv = *reinterpret_cast<const ulonglong2*>(sm + oW1 + (k + j) * 128 + lane * 4);
#pragma unroll
                for (int i = 0; i < 4; i++) {
                    unsigned long long xx = dup2(x4[i][j]);
                    acc[i][0] = fma2(wv.x, xx, acc[i][0]);
                    acc[i][1] = fma2(wv.y, xx, acc[i][1]);
                }
            }
        }
        __syncwarp();
#pragma unroll
        for (int i = 0; i < 4; i++) {
            float a0, a1, a2v, a3;
            unpack2(acc[i][0], a0, a1);
            unpack2(acc[i][1], a2v, a3);
            reinterpret_cast<float4*>(hs + i * 128)[lane] =
                make_float4(gelu_exact(a0), gelu_exact(a1), gelu_exact(a2v), gelu_exact(a3));
        }
        __syncwarp();

        // ---- layer 2 ----
        unsigned long long ac2[4][2];
#pragma unroll
        for (int i = 0; i < 4; i++) {
            ac2[i][0] = pack2(bv2.x, bv2.y);
            ac2[i][1] = pack2(bv2.z, bv2.w);
        }
        for (int k = 0; k < 128; k += 4) {
            float x4[4][4];
#pragma unroll
            for (int i = 0; i < 4; i++) {
                float4 q = *reinterpret_cast<const float4*>(hs + i * 128 + k);
                x4[i][0] = q.x; x4[i][1] = q.y; x4[i][2] = q.z; x4[i][3] = q.w;
            }
#pragma unroll
            for (int j = 0; j < 4; j++) {
                ulonglong2 wv = *reinterpret_cast<const ulonglong2*>(sm + oW2 + (k + j) * 128 + lane * 4);
#pragma unroll
                for (int i = 0; i < 4; i++) {
                    unsigned long long xx = dup2(x4[i][j]);
                    ac2[i][0] = fma2(wv.x, xx, ac2[i][0]);
                    ac2[i][1] = fma2(wv.y, xx, ac2[i][1]);
                }
            }
        }
        __syncwarp();
#pragma unroll
        for (int i = 0; i < 4; i++) {
            float a0, a1, a2v, a3;
            unpack2(ac2[i][0], a0, a1);
            unpack2(ac2[i][1], a2v, a3);
            reinterpret_cast<float4*>(hs + i * 128)[lane] =
                make_float4(gelu_exact(a0), gelu_exact(a1), gelu_exact(a2v), gelu_exact(a3));
        }
        __syncwarp();

        // ---- layer 3 (66 cols; lane -> {l, 32+l, 64+l<2}) ----
        unsigned long long c01[4];
        float c2[4];
#pragma unroll
        for (int i = 0; i < 4; i++) { c01[i] = pack2(bc0, bc1); c2[i] = bc2; }
        for (int k = 0; k < 128; k += 4) {
            float x4[4][4];
#pragma unroll
            for (int i = 0; i < 4; i++) {
                float4 q = *reinterpret_cast<const float4*>(hs + i * 128 + k);
                x4[i][0] = q.x; x4[i][1] = q.y; x4[i][2] = q.z; x4[i][3] = q.w;
            }
#pragma unroll
            for (int j = 0; j < 4; j++) {
                const float* wr = sm + oW3 + (k + j) * 66;
                unsigned long long w01 = pack2(wr[lane], wr[32 + lane]);
                float w2v = wr[64 + lane];
#pragma unroll
                for (int i = 0; i < 4; i++) {
                    c01[i] = fma2(w01, dup2(x4[i][j]), c01[i]);
                    c2[i] = fmaf(w2v, x4[i][j], c2[i]);
                }
            }
        }

#pragma unroll
        for (int i = 0; i < 4; i++) {
            int a = base + i;
            if (a >= NAT) break;
            float c0, c1;
            unpack2(c01[i], c0, c1);
            if (lane == 0)      dq[a] = c0;
            else if (lane == 1) fo[a] = c0;
            else                da[(size_t)a * 64 + (lane - 2)] = c0;
            da[(size_t)a * 64 + (30 + lane)] = c1;
            if (lane < 2) da[(size_t)a * 64 + (62 + lane)] = c2[i];
        }
    }
}

// ---------------- host launcher ----------------
extern "C" void kernel_launch(void* const* d_in, const int* in_sizes, int n_in,
                              void* d_out, int out_size) {
    const float *emb = 0, *pc = 0, *gs = 0, *gv = 0, *agh = 0;
    const float *W1 = 0, *b1 = 0, *W2 = 0, *b2 = 0, *W3 = 0, *b3 = 0;
    const int* pidx = 0;

    for (int i = 0; i < n_in; i++) {
        switch (in_sizes[i]) {
            case 3200000:  emb = (const float*)d_in[i]; break;
            case 50000:    pc  = (const float*)d_in[i]; break;
            case 16000000: gs  = (const float*)d_in[i]; break;
            case 48000000: gv  = (const float*)d_in[i]; break;
            case 32768:    agh = (const float*)d_in[i]; break;
            case 16512:    W1  = (const float*)d_in[i]; break;
            case 16384:    W2  = (const float*)d_in[i]; break;
            case 8448:     W3  = (const float*)d_in[i]; break;
            case 128:      if (!b1) b1 = (const float*)d_in[i];
                           else     b2 = (const float*)d_in[i]; break;
            case 66:       b3  = (const float*)d_in[i]; break;
            case 2000000:  pidx = (const int*)d_in[i]; break;
            default: break;
        }
    }
    float* out = (float*)d_out;
    (void)out_size;

    cudaFuncSetAttribute(k_atom, cudaFuncAttributeMaxDynamicSharedMemorySize, 131072);
    cudaFuncSetAttribute(k_mlp,  cudaFuncAttributeMaxDynamicSharedMemorySize, SMEM_MLP);

    const int* idxj = pidx + NP;   // pair_indices[1]

    k_zero<<<(NAT + 255) / 256, 256>>>();
    k_hist<<<(NP + 255) / 256, 256>>>(gs, idxj);
    k_scan<<<1, 1024>>>();
    k_place<<<(NP + 255) / 256, 256>>>(idxj);
    k_gather<<<(2 * NAT + 255) / 256, 256>>>(gv);
    k_atom<<<NSM, 512, 131072>>>(emb, pc, agh);
    k_mlp<<<NSM, 512, SMEM_MLP>>>(W1, b1, W2, b2, W3, b3, out);
}

// round 5
// speedup vs baseline: 1.0713x; 1.0034x over previous
#include <cuda_runtime.h>
#include <math.h>
#include <stdint.h>

#define NAT   50000
#define NP    1000000
#define MSGS  104
#define NSM   152

// ---------------- device scratch ----------------
__device__ float g_Msum[(size_t)NAT * 136];
__device__ float g_S[NAT];
__device__ float g_msg[(size_t)NAT * MSGS];
__device__ int   g_cnt[NAT];
__device__ int   g_off[NAT + 1];
__device__ int   g_cur[NAT];
__device__ int   g_plist[NP];

// ---------------- f32x2 helpers ----------------
__device__ __forceinline__ unsigned long long pack2(float x, float y) {
    unsigned long long r; asm("mov.b64 %0, {%1, %2};" : "=l"(r) : "f"(x), "f"(y)); return r;
}
__device__ __forceinline__ unsigned long long dup2(float x) {
    unsigned long long r; asm("mov.b64 %0, {%1, %1};" : "=l"(r) : "f"(x)); return r;
}
__device__ __forceinline__ void unpack2(unsigned long long v, float& x, float& y) {
    asm("mov.b64 {%0, %1}, %2;" : "=f"(x), "=f"(y) : "l"(v));
}
__device__ __forceinline__ unsigned long long fma2(unsigned long long a, unsigned long long b,
                                                   unsigned long long c) {
    unsigned long long d;
    asm("fma.rn.f32x2 %0, %1, %2, %3;" : "=l"(d) : "l"(a), "l"(b), "l"(c));
    return d;
}

__device__ __forceinline__ float gelu_exact(float x) {
    return 0.5f * x * (1.0f + erff(x * 0.70710678118654752440f));
}

// upper-tri index (compile-time under full unroll)
#define EIDX(g, gp) ((g) * 16 - ((g) * ((g) - 1)) / 2 + ((gp) - (g)))

// ---------------- k_zero ----------------
__global__ void k_zero() {
    int i = blockIdx.x * blockDim.x + threadIdx.x;
    if (i < NAT) { g_cnt[i] = 0; g_S[i] = 0.f; }
}

// ---------------- k_hist: count pairs per atom + S accumulation ----------------
__global__ void __launch_bounds__(256) k_hist(const float* __restrict__ gs,
                                              const int* __restrict__ idxj) {
    int p = blockIdx.x * 256 + threadIdx.x;
    if (p >= NP) return;
    const float4* gs4 = reinterpret_cast<const float4*>(gs) + (size_t)p * 4;
    float s = 0.f;
#pragma unroll
    for (int k = 0; k < 4; k++) {
        float4 t = __ldg(gs4 + k);
        s += (t.x + t.y) + (t.z + t.w);
    }
    int a = __ldg(idxj + p);
    if (a < 0 || a >= NAT) return;
    atomicAdd(&g_cnt[a], 1);
    atomicAdd(&g_S[a], s);
}

// ---------------- k_scan: exclusive prefix (1 block, 1024 threads) ----------------
__global__ void __launch_bounds__(1024) k_scan() {
    __shared__ int ts[1024];
    int t = threadIdx.x;
    const int CH = (NAT + 1023) / 1024;   // 49
    int base = t * CH;
    int s0 = 0, s1 = 0, s2 = 0, s3 = 0;
    for (int j = 0; j + 3 < CH; j += 4) {
        int a = base + j;
        s0 += (a + 0 < NAT) ? g_cnt[a + 0] : 0;
        s1 += (a + 1 < NAT) ? g_cnt[a + 1] : 0;
        s2 += (a + 2 < NAT) ? g_cnt[a + 2] : 0;
        s3 += (a + 3 < NAT) ? g_cnt[a + 3] : 0;
    }
    for (int j = CH & ~3; j < CH; j++) {
        int a = base + j;
        s0 += (a < NAT) ? g_cnt[a] : 0;
    }
    ts[t] = s0 + s1 + s2 + s3;
    __syncthreads();
    for (int off = 1; off < 1024; off <<= 1) {
        int v = (t >= off) ? ts[t - off] : 0;
        __syncthreads();
        ts[t] += v;
        __syncthreads();
    }
    int run = (t == 0) ? 0 : ts[t - 1];
    for (int j = 0; j < CH; j++) {
        int a = base + j;
        if (a < NAT) {
            g_off[a] = run;
            g_cur[a] = run;
            run += g_cnt[a];
        } else if (a == NAT) {
            g_off[NAT] = run;
        }
    }
}

// ---------------- k_place: bucket pair ids ----------------
__global__ void __launch_bounds__(256) k_place(const int* __restrict__ idxj) {
    int p = blockIdx.x * 256 + threadIdx.x;
    if (p >= NP) return;
    int a = __ldg(idxj + p);
    if (a < 0 || a >= NAT) return;
    int pos = atomicAdd(&g_cur[a], 1);
    g_plist[pos] = p;
}

// ---------------- k_gather: per-atom Gram accumulation (no atomics) ----------------
// t < NAT: half 0 (entries 0..67); t >= NAT: half 1 (entries 68..135).
__global__ void __launch_bounds__(256) k_gather(const float* __restrict__ gv) {
    int t = blockIdx.x * 256 + threadIdx.x;
    if (t >= 2 * NAT) return;
    int half = (t >= NAT) ? 1 : 0;
    int a = half ? (t - NAT) : t;

    float acc[68];
#pragma unroll
    for (int i = 0; i < 68; i++) acc[i] = 0.f;

    int beg = g_off[a], end = g_off[a + 1];

    if (!half) {
        for (int j = beg; j < end; j++) {
            int p = g_plist[j];
            float v[48];
            const float4* gv4 = reinterpret_cast<const float4*>(gv) + (size_t)p * 12;
#pragma unroll
            for (int k = 0; k < 12; k++) {
                float4 q = __ldg(gv4 + k);
                v[4 * k] = q.x; v[4 * k + 1] = q.y; v[4 * k + 2] = q.z; v[4 * k + 3] = q.w;
            }
#pragma unroll
            for (int g = 0; g < 16; g++)
#pragma unroll
                for (int gp = g; gp < 16; gp++) {
                    const int e = EIDX(g, gp);
                    if (e < 68) {
                        float m = v[g] * v[gp] + v[16 + g] * v[16 + gp] + v[32 + g] * v[32 + gp];
                        acc[e] += m;
                    }
                }
        }
    } else {
        for (int j = beg; j < end; j++) {
            int p = g_plist[j];
            float v[48];
            const float4* gv4 = reinterpret_cast<const float4*>(gv) + (size_t)p * 12;
#pragma unroll
            for (int k = 0; k < 12; k++) {
                float4 q = __ldg(gv4 + k);
                v[4 * k] = q.x; v[4 * k + 1] = q.y; v[4 * k + 2] = q.z; v[4 * k + 3] = q.w;
            }
#pragma unroll
            for (int g = 0; g < 16; g++)
#pragma unroll
                for (int gp = g; gp < 16; gp++) {
                    const int e = EIDX(g, gp);
                    if (e >= 68) {
                        float m = v[g] * v[gp] + v[16 + g] * v[16 + gp] + v[32 + g] * v[32 + gp];
                        acc[e - 68] += m;
                    }
                }
        }
    }

    float4* mr4 = reinterpret_cast<float4*>(g_Msum + (size_t)a * 136 + half * 68);
#pragma unroll
    for (int i = 0; i < 17; i++)
        mr4[i] = make_float4(acc[4 * i], acc[4 * i + 1], acc[4 * i + 2], acc[4 * i + 3]);
}

// ---------------- k_atom: T = emb @ agh (f32x2), quad form -> msg ----------------
// agh in smem, relaid as [f][g2][h][2] so (g,g+1) pairs are contiguous b64.
__global__ void __launch_bounds__(512) k_atom(const float* __restrict__ emb,
                                              const float* __restrict__ pc,
                                              const float* __restrict__ agh) {
    extern __shared__ float aghs[];
    int tid = threadIdx.x;
    for (int i = tid; i < 32768; i += 512) {
        int f = i >> 9, rem = i & 511, g = rem >> 5, h = rem & 31;
        aghs[f * 512 + (g >> 1) * 64 + h * 2 + (g & 1)] = __ldg(agh + i);
    }
    __syncthreads();

    int lane = tid & 31, wid = tid >> 5;
    int gw = blockIdx.x * 16 + wid;
    int GW = gridDim.x * 16;

    for (int base = gw * 4; base < NAT; base += GW * 4) {
        float e0[4], e1[4];
#pragma unroll
        for (int i = 0; i < 4; i++) {
            int ai = (base + i < NAT) ? base + i : NAT - 1;
            e0[i] = __ldg(emb + (size_t)ai * 64 + lane);
            e1[i] = __ldg(emb + (size_t)ai * 64 + 32 + lane);
        }

        unsigned long long T2[4][8];
#pragma unroll
        for (int i = 0; i < 4; i++)
#pragma unroll
            for (int g2 = 0; g2 < 8; g2++) T2[i][g2] = 0ull;

        // f = 0..31 from e0, f = 32..63 from e1
#pragma unroll 4
        for (int fl = 0; fl < 32; fl++) {
            unsigned long long x0 = dup2(__shfl_sync(0xffffffffu, e0[0], fl));
            unsigned long long x1 = dup2(__shfl_sync(0xffffffffu, e0[1], fl));
            unsigned long long x2 = dup2(__shfl_sync(0xffffffffu, e0[2], fl));
            unsigned long long x3 = dup2(__shfl_sync(0xffffffffu, e0[3], fl));
            const unsigned long long* ap =
                reinterpret_cast<const unsigned long long*>(aghs + fl * 512) + lane;
#pragma unroll
            for (int g2 = 0; g2 < 8; g2++) {
                unsigned long long av = ap[g2 * 32];
                T2[0][g2] = fma2(x0, av, T2[0][g2]);
                T2[1][g2] = fma2(x1, av, T2[1][g2]);
                T2[2][g2] = fma2(x2, av, T2[2][g2]);
                T2[3][g2] = fma2(x3, av, T2[3][g2]);
            }
        }
#pragma unroll 4
        for (int fl = 0; fl < 32; fl++) {
            unsigned long long x0 = dup2(__shfl_sync(0xffffffffu, e1[0], fl));
            unsigned long long x1 = dup2(__shfl_sync(0xffffffffu, e1[1], fl));
            unsigned long long x2 = dup2(__shfl_sync(0xffffffffu, e1[2], fl));
            unsigned long long x3 = dup2(__shfl_sync(0xffffffffu, e1[3], fl));
            const unsigned long long* ap =
                reinterpret_cast<const unsigned long long*>(aghs + (32 + fl) * 512) + lane;
#pragma unroll
            for (int g2 = 0; g2 < 8; g2++) {
                unsigned long long av = ap[g2 * 32];
                T2[0][g2] = fma2(x0, av, T2[0][g2]);
                T2[1][g2] = fma2(x1, av, T2[1][g2]);
                T2[2][g2] = fma2(x2, av, T2[2][g2]);
                T2[3][g2] = fma2(x3, av, T2[3][g2]);
            }
        }

#pragma unroll
        for (int i = 0; i < 4; i++) {
            int a = base + i;
            if (a >= NAT) break;
            float T[16];
#pragma unroll
            for (int g2 = 0; g2 < 8; g2++) unpack2(T2[i][g2], T[2 * g2], T[2 * g2 + 1]);

            const float* mr = g_Msum + (size_t)a * 136;
            float mv0 = mr[lane], mv1 = mr[32 + lane], mv2 = mr[64 + lane], mv3 = mr[96 + lane];
            float mv4 = (lane < 8) ? mr[128 + lane] : 0.f;
            float Sv = g_S[a];
            float qv = __ldg(pc + a);

            float qd = 0.f, qo = 0.f;
#pragma unroll
            for (int g = 0; g < 16; g++)
#pragma unroll
                for (int gp = g; gp < 16; gp++) {
                    const int e = EIDX(g, gp);
                    float msrc = (e < 32) ? mv0 : (e < 64) ? mv1 : (e < 96) ? mv2
                               : (e < 128) ? mv3 : mv4;
                    float m = __shfl_sync(0xffffffffu, msrc, e & 31);
                    float t = T[g] * T[gp];
                    if (g == gp) qd = fmaf(m, t, qd);
                    else         qo = fmaf(m, t, qo);
                }
            float Q = fmaf(2.f, qo, qd);

            float* mg = g_msg + (size_t)a * MSGS;
            mg[lane]      = e0[i] * Sv;
            mg[32 + lane] = e1[i] * Sv;
            mg[64 + lane] = Q;
            if (lane < 8) mg[96 + lane] = (lane == 0) ? qv * Sv : 0.f;
        }
    }
}

// ---------------- k_mlp: 97->128->128->66 with f32x2, 512 threads ----------------
#define oW1 0              /* 100 x 128 (rows 97..99 zero)      */
#define oW2 12800          /* 128 x 128                          */
#define oW3 29184          /* 128 x 66 + 64 pad                  */
#define oB1 37696
#define oB2 37824
#define oB3 37952          /* 72 (66 + pad)                      */
#define oHS 38024          /* 16 warps * 4 atoms * 128           */
#define oMS 46216          /* 16 warps * 4 atoms * 104           */
#define SMEM_MLP (52872 * 4)

__global__ void __launch_bounds__(512) k_mlp(const float* __restrict__ W1,
                                             const float* __restrict__ b1,
                                             const float* __restrict__ W2,
                                             const float* __restrict__ b2,
                                             const float* __restrict__ W3,
                                             const float* __restrict__ b3,
                                             float* __restrict__ out) {
    extern __shared__ float sm[];
    int tid = threadIdx.x;
    for (int i = tid; i < 12800; i += 512) sm[oW1 + i] = (i < 12416) ? W1[i] : 0.f;
    for (int i = tid; i < 16384; i += 512) sm[oW2 + i] = W2[i];
    for (int i = tid; i < 8512; i += 512) sm[oW3 + i] = (i < 8448) ? W3[i] : 0.f;
    if (tid < 128) { sm[oB1 + tid] = b1[tid]; sm[oB2 + tid] = b2[tid]; }
    if (tid < 72)  sm[oB3 + tid] = (tid < 66) ? b3[tid] : 0.f;
    __syncthreads();

    int lane = tid & 31, w = tid >> 5;
    float* ms = sm + oMS + w * 416;
    float* hs = sm + oHS + w * 512;
    float4 bv1 = reinterpret_cast<const float4*>(sm + oB1)[lane];
    float4 bv2 = reinterpret_cast<const float4*>(sm + oB2)[lane];
    float bc0 = sm[oB3 + lane];
    float bc1 = sm[oB3 + 32 + lane];
    float bc2 = (lane < 2) ? sm[oB3 + 64 + lane] : 0.f;

    float* da = out;
    float* dq = out + (size_t)NAT * 64;
    float* fo = out + (size_t)NAT * 65;

    int gw = blockIdx.x * 16 + w, GW = gridDim.x * 16;
    for (int base = gw * 4; base < NAT; base += GW * 4) {
#pragma unroll
        for (int i = 0; i < 4; i++) {
            int ai = (base + i < NAT) ? base + i : NAT - 1;
            const float4* mrow = reinterpret_cast<const float4*>(g_msg + (size_t)ai * MSGS);
            if (lane < 26) reinterpret_cast<float4*>(ms + i * 104)[lane] = __ldg(mrow + lane);
        }
        __syncwarp();

        // ---- layer 1 (100 rows incl. zero pad) ----
        unsigned long long acc[4][2];
#pragma unroll
        for (int i = 0; i < 4; i++) {
            acc[i][0] = pack2(bv1.x, bv1.y);
            acc[i][1] = pack2(bv1.z, bv1.w);
        }
        for (int k = 0; k < 100; k += 4) {
            float x4[4][4];
#pragma unroll
            for (int i = 0; i < 4; i++) {
                float4 q = *reinterpret_cast<const float4*>(ms + i * 104 + k);
                x4[i][0] = q.x; x4[i][1] = q.y; x4[i][2] = q.z; x4[i][3] = q.w;
            }
#pragma unroll
            for (int j = 0; j < 4; j++) {
                ulonglong2 wv = *reinterpret_cast<const ulonglong2*>(sm + oW1 + (k + j) * 128 + lane * 4);
#pragma unroll
                for (int i = 0; i < 4; i++) {
                    unsigned long long xx = dup2(x4[i][j]);
                    acc[i][0] = fma2(wv.x, xx, acc[i][0]);
                    acc[i][1] = fma2(wv.y, xx, acc[i][1]);
                }
            }
        }
        __syncwarp();
#pragma unroll
        for (int i = 0; i < 4; i++) {
            float a0, a1, a2v, a3;
            unpack2(acc[i][0], a0, a1);
            unpack2(acc[i][1], a2v, a3);
            reinterpret_cast<float4*>(hs + i * 128)[lane] =
                make_float4(gelu_exact(a0), gelu_exact(a1), gelu_exact(a2v), gelu_exact(a3));
        }
        __syncwarp();

        // ---- layer 2 ----
        unsigned long long ac2[4][2];
#pragma unroll
        for (int i = 0; i < 4; i++) {
            ac2[i][0] = pack2(bv2.x, bv2.y);
            ac2[i][1] = pack2(bv2.z, bv2.w);
        }
        for (int k = 0; k < 128; k += 4) {
            float x4[4][4];
#pragma unroll
            for (int i = 0; i < 4; i++) {
                float4 q = *reinterpret_cast<const float4*>(hs + i * 128 + k);
                x4[i][0] = q.x; x4[i][1] = q.y; x4[i][2] = q.z; x4[i][3] = q.w;
            }
#pragma unroll
            for (int j = 0; j < 4; j++) {
                ulonglong2 wv = *reinterpret_cast<const ulonglong2*>(sm + oW2 + (k + j) * 128 + lane * 4);
#pragma unroll
                for (int i = 0; i < 4; i++) {
                    unsigned long long xx = dup2(x4[i][j]);
                    ac2[i][0] = fma2(wv.x, xx, ac2[i][0]);
                    ac2[i][1] = fma2(wv.y, xx, ac2[i][1]);
                }
            }
        }
        __syncwarp();
#pragma unroll
        for (int i = 0; i < 4; i++) {
            float a0, a1, a2v, a3;
            unpack2(ac2[i][0], a0, a1);
            unpack2(ac2[i][1], a2v, a3);
            reinterpret_cast<float4*>(hs + i * 128)[lane] =
                make_float4(gelu_exact(a0), gelu_exact(a1), gelu_exact(a2v), gelu_exact(a3));
        }
        __syncwarp();

        // ---- layer 3 (66 cols; lane -> {l, 32+l, 64+l<2}) ----
        unsigned long long c01[4];
        float c2[4];
#pragma unroll
        for (int i = 0; i < 4; i++) { c01[i] = pack2(bc0, bc1); c2[i] = bc2; }
        for (int k = 0; k < 128; k += 4) {
            float x4[4][4];
#pragma unroll
            for (int i = 0; i < 4; i++) {
                float4 q = *reinterpret_cast<const float4*>(hs + i * 128 + k);
                x4[i][0] = q.x; x4[i][1] = q.y; x4[i][2] = q.z; x4[i][3] = q.w;
            }
#pragma unroll
            for (int j = 0; j < 4; j++) {
                const float* wr = sm + oW3 + (k + j) * 66;
                unsigned long long w01 = pack2(wr[lane], wr[32 + lane]);
                float w2v = wr[64 + lane];
#pragma unroll
                for (int i = 0; i < 4; i++) {
                    c01[i] = fma2(w01, dup2(x4[i][j]), c01[i]);
                    c2[i] = fmaf(w2v, x4[i][j], c2[i]);
                }
            }
        }

#pragma unroll
        for (int i = 0; i < 4; i++) {
            int a = base + i;
            if (a >= NAT) break;
            float c0, c1;
            unpack2(c01[i], c0, c1);
            if (lane == 0)      dq[a] = c0;
            else if (lane == 1) fo[a] = c0;
            else                da[(size_t)a * 64 + (lane - 2)] = c0;
            da[(size_t)a * 64 + (30 + lane)] = c1;
            if (lane < 2) da[(size_t)a * 64 + (62 + lane)] = c2[i];
        }
    }
}

// ---------------- host launcher ----------------
extern "C" void kernel_launch(void* const* d_in, const int* in_sizes, int n_in,
                              void* d_out, int out_size) {
    const float *emb = 0, *pc = 0, *gs = 0, *gv = 0, *agh = 0;
    const float *W1 = 0, *b1 = 0, *W2 = 0, *b2 = 0, *W3 = 0, *b3 = 0;
    const int* pidx = 0;

    for (int i = 0; i < n_in; i++) {
        switch (in_sizes[i]) {
            case 3200000:  emb = (const float*)d_in[i]; break;
            case 50000:    pc  = (const float*)d_in[i]; break;
            case 16000000: gs  = (const float*)d_in[i]; break;
            case 48000000: gv  = (const float*)d_in[i]; break;
            case 32768:    agh = (const float*)d_in[i]; break;
            case 16512:    W1  = (const float*)d_in[i]; break;
            case 16384:    W2  = (const float*)d_in[i]; break;
            case 8448:     W3  = (const float*)d_in[i]; break;
            case 128:      if (!b1) b1 = (const float*)d_in[i];
                           else     b2 = (const float*)d_in[i]; break;
            case 66:       b3  = (const float*)d_in[i]; break;
            case 2000000:  pidx = (const int*)d_in[i]; break;
            default: break;
        }
    }
    float* out = (float*)d_out;
    (void)out_size;

    cudaFuncSetAttribute(k_atom, cudaFuncAttributeMaxDynamicSharedMemorySize, 131072);
    cudaFuncSetAttribute(k_mlp,  cudaFuncAttributeMaxDynamicSharedMemorySize, SMEM_MLP);

    const int* idxj = pidx + NP;   // pair_indices[1]

    k_zero<<<(NAT + 255) / 256, 256>>>();
    k_hist<<<(NP + 255) / 256, 256>>>(gs, idxj);
    k_scan<<<1, 1024>>>();
    k_place<<<(NP + 255) / 256, 256>>>(idxj);
    k_gather<<<(2 * NAT + 255) / 256, 256>>>(gv);
    k_atom<<<NSM, 512, 131072>>>(emb, pc, agh);
    k_mlp<<<NSM, 512, SMEM_MLP>>>(W1, b1, W2, b2, W3, b3, out);
}